// round 1
// baseline (speedup 1.0000x reference)
#include <cuda_runtime.h>

// Hopf oscillator scan.
// Shapes: X_r, X_i: [bs=8, T=64, d=32, d=32, nk=32] fp32; omegas: [32,32,32].
// Output: concat(out_r, out_i), each [8,64,32,32,32] fp32.
//
// Per-channel recurrence (channel = (b,i,j,k), scan over t):
//   input_r   = 20 * xr * cos(phi)
//   input_phi = 20 * xi * sin(phi)
//   r   += ((1 - r^2) * r + input_r) * 0.01
//   phi += (omega - input_phi) * 0.01
//   out_r[t] = r * cos(phi);  out_i[t] = r * sin(phi)
//
// One thread owns 4 adjacent channels (float4), loops t=0..63 with 1-deep
// prefetch. cos/sin of the *new* phi are carried to the next iteration so we
// do exactly one __sincosf per channel-step.

#define HOPF_DT      0.01f
#define HOPF_SCALER  20.0f

static constexpr int BS  = 8;
static constexpr int T   = 64;
static constexpr int CPB = 32 * 32 * 32;   // channels per batch = 32768
static constexpr int V   = CPB / 4;        // float4 vectors per (b,t) slab = 8192

__global__ __launch_bounds__(256)
void hopf_scan_kernel(const float4* __restrict__ Xr,
                      const float4* __restrict__ Xi,
                      const float4* __restrict__ Om,
                      float4* __restrict__ OutR,
                      float4* __restrict__ OutI)
{
    const int u  = blockIdx.x * blockDim.x + threadIdx.x;  // vec4 id, 0..65535
    const int b  = u / V;
    const int c4 = u % V;

    const float4 om = Om[c4];
    const float omv[4] = {om.x, om.y, om.z, om.w};

    float r[4], phi[4], cs[4], sn[4];
#pragma unroll
    for (int j = 0; j < 4; ++j) { r[j] = 1.0f; phi[j] = 0.0f; cs[j] = 1.0f; sn[j] = 0.0f; }

    int off = (b * T) * V + c4;      // max index < 4.2M, int is safe
    float4 xr = Xr[off];
    float4 xi = Xi[off];

#pragma unroll 4
    for (int t = 0; t < T; ++t) {
        const int offn = off + ((t + 1 < T) ? V : 0);
        const float4 xrn = Xr[offn];
        const float4 xin = Xi[offn];

        const float xrv[4] = {xr.x, xr.y, xr.z, xr.w};
        const float xiv[4] = {xi.x, xi.y, xi.z, xi.w};

        float orv[4], oiv[4];
#pragma unroll
        for (int j = 0; j < 4; ++j) {
            const float input_r   = HOPF_SCALER * xrv[j] * cs[j];
            const float input_phi = HOPF_SCALER * xiv[j] * sn[j];
            const float rr = r[j];
            r[j]   = rr + ((1.0f - rr * rr) * rr + input_r) * HOPF_DT;
            phi[j] = phi[j] + (omv[j] - input_phi) * HOPF_DT;
            __sincosf(phi[j], &sn[j], &cs[j]);
            orv[j] = r[j] * cs[j];
            oiv[j] = r[j] * sn[j];
        }

        OutR[off] = make_float4(orv[0], orv[1], orv[2], orv[3]);
        OutI[off] = make_float4(oiv[0], oiv[1], oiv[2], oiv[3]);

        off = offn;
        xr  = xrn;
        xi  = xin;
    }
}

extern "C" void kernel_launch(void* const* d_in, const int* in_sizes, int n_in,
                              void* d_out, int out_size)
{
    const float4* Xr = (const float4*)d_in[0];
    const float4* Xi = (const float4*)d_in[1];
    const float4* Om = (const float4*)d_in[2];

    float* out = (float*)d_out;
    const int n_elem = BS * T * CPB;            // 16,777,216 per output tensor
    float4* OutR = (float4*)out;
    float4* OutI = (float4*)(out + n_elem);

    const int n_threads = (BS * CPB) / 4;       // 65536
    hopf_scan_kernel<<<n_threads / 256, 256>>>(Xr, Xi, Om, OutR, OutI);
}

// round 2
// speedup vs baseline: 1.0355x; 1.0355x over previous
#include <cuda_runtime.h>

// Hopf oscillator scan — R2: prefetch depth 4 + streaming load/store hints.
// Shapes: X_r, X_i: [bs=8, T=64, 32,32,32] fp32; omegas: [32,32,32].
// Output: concat(out_r, out_i).
//
// HBM-bound kernel (256 MB total traffic). R1 hit only 64% DRAM because
// bytes-in-flight (~2MB) < BW*latency (~3MB). Depth-4 ring buffer of
// prefetched (xr, xi) float4s raises in-flight bytes to ~6-8MB.

#define HOPF_DT      0.01f
#define HOPF_SCALER  20.0f

static constexpr int BS  = 8;
static constexpr int T   = 64;
static constexpr int CPB = 32 * 32 * 32;   // channels per batch = 32768
static constexpr int V   = CPB / 4;        // float4 vectors per (b,t) slab = 8192
static constexpr int PF  = 4;              // prefetch depth (power of 2)

__device__ __forceinline__ float4 ldcs4(const float4* p) {
    float4 v;
    asm volatile("ld.global.cs.v4.f32 {%0,%1,%2,%3}, [%4];"
                 : "=f"(v.x), "=f"(v.y), "=f"(v.z), "=f"(v.w) : "l"(p));
    return v;
}

__device__ __forceinline__ void stcs4(float4* p, float4 v) {
    asm volatile("st.global.cs.v4.f32 [%0], {%1,%2,%3,%4};"
                 :: "l"(p), "f"(v.x), "f"(v.y), "f"(v.z), "f"(v.w) : "memory");
}

__global__ __launch_bounds__(256)
void hopf_scan_kernel(const float4* __restrict__ Xr,
                      const float4* __restrict__ Xi,
                      const float4* __restrict__ Om,
                      float4* __restrict__ OutR,
                      float4* __restrict__ OutI)
{
    const int u  = blockIdx.x * blockDim.x + threadIdx.x;  // vec4 id, 0..65535
    const int b  = u / V;
    const int c4 = u % V;

    const float4 om = Om[c4];
    const float omv[4] = {om.x, om.y, om.z, om.w};

    float r[4], phi[4], cs[4], sn[4];
#pragma unroll
    for (int j = 0; j < 4; ++j) { r[j] = 1.0f; phi[j] = 0.0f; cs[j] = 1.0f; sn[j] = 0.0f; }

    const int base = (b * T) * V + c4;

    // Preload stages 0..PF-2 (t = 0..2)
    float4 xrb[PF], xib[PF];
#pragma unroll
    for (int p = 0; p < PF - 1; ++p) {
        xrb[p] = ldcs4(Xr + base + p * V);
        xib[p] = ldcs4(Xi + base + p * V);
    }

#pragma unroll 4
    for (int t = 0; t < T; ++t) {
        // Prefetch t+PF-1 into its ring slot (stays in-bounds by clamping).
        {
            const int tp  = t + PF - 1;
            const int offp = base + ((tp < T) ? tp : (T - 1)) * V;
            xrb[tp & (PF - 1)] = ldcs4(Xr + offp);
            xib[tp & (PF - 1)] = ldcs4(Xi + offp);
        }

        const float4 xr = xrb[t & (PF - 1)];
        const float4 xi = xib[t & (PF - 1)];
        const float xrv[4] = {xr.x, xr.y, xr.z, xr.w};
        const float xiv[4] = {xi.x, xi.y, xi.z, xi.w};

        float orv[4], oiv[4];
#pragma unroll
        for (int j = 0; j < 4; ++j) {
            const float input_r   = HOPF_SCALER * xrv[j] * cs[j];
            const float input_phi = HOPF_SCALER * xiv[j] * sn[j];
            const float rr = r[j];
            r[j]   = rr + ((1.0f - rr * rr) * rr + input_r) * HOPF_DT;
            phi[j] = phi[j] + (omv[j] - input_phi) * HOPF_DT;
            __sincosf(phi[j], &sn[j], &cs[j]);
            orv[j] = r[j] * cs[j];
            oiv[j] = r[j] * sn[j];
        }

        const int off = base + t * V;
        stcs4(OutR + off, make_float4(orv[0], orv[1], orv[2], orv[3]));
        stcs4(OutI + off, make_float4(oiv[0], oiv[1], oiv[2], oiv[3]));
    }
}

extern "C" void kernel_launch(void* const* d_in, const int* in_sizes, int n_in,
                              void* d_out, int out_size)
{
    const float4* Xr = (const float4*)d_in[0];
    const float4* Xi = (const float4*)d_in[1];
    const float4* Om = (const float4*)d_in[2];

    float* out = (float*)d_out;
    const int n_elem = BS * T * CPB;            // 16,777,216 per output tensor
    float4* OutR = (float4*)out;
    float4* OutI = (float4*)(out + n_elem);

    const int n_threads = (BS * CPB) / 4;       // 65536
    hopf_scan_kernel<<<n_threads / 256, 256>>>(Xr, Xi, Om, OutR, OutI);
}

// round 3
// speedup vs baseline: 1.0800x; 1.0430x over previous
#include <cuda_runtime.h>

// Hopf oscillator scan — R3: 2 channels/thread (float2), 2x warp count.
// R2 showed prefetch depth alone doesn't raise DRAM% (66%): with only 14
// warps/SM, warps spend their time in the per-iteration compute chain and
// can't keep the memory pipe fed. Double TLP: 131072 threads, 28 warps/SM.

#define HOPF_DT      0.01f
#define HOPF_SCALER  20.0f

static constexpr int BS  = 8;
static constexpr int T   = 64;
static constexpr int CPB = 32 * 32 * 32;   // channels per batch = 32768
static constexpr int V2  = CPB / 2;        // float2 vectors per (b,t) slab = 16384
static constexpr int PF  = 4;              // prefetch depth (power of 2)

__device__ __forceinline__ float2 ldcs2(const float2* p) {
    float2 v;
    asm volatile("ld.global.cs.v2.f32 {%0,%1}, [%2];"
                 : "=f"(v.x), "=f"(v.y) : "l"(p));
    return v;
}

__device__ __forceinline__ void stcs2(float2* p, float2 v) {
    asm volatile("st.global.cs.v2.f32 [%0], {%1,%2};"
                 :: "l"(p), "f"(v.x), "f"(v.y) : "memory");
}

__global__ __launch_bounds__(256)
void hopf_scan_kernel(const float2* __restrict__ Xr,
                      const float2* __restrict__ Xi,
                      const float2* __restrict__ Om,
                      float2* __restrict__ OutR,
                      float2* __restrict__ OutI)
{
    const int u  = blockIdx.x * blockDim.x + threadIdx.x;  // vec2 id, 0..131071
    const int b  = u / V2;
    const int c2 = u % V2;

    const float2 om = Om[c2];
    const float omv[2] = {om.x, om.y};

    float r[2], phi[2], cs[2], sn[2];
#pragma unroll
    for (int j = 0; j < 2; ++j) { r[j] = 1.0f; phi[j] = 0.0f; cs[j] = 1.0f; sn[j] = 0.0f; }

    const int base = (b * T) * V2 + c2;

    // Preload stages t = 0..PF-2
    float2 xrb[PF], xib[PF];
#pragma unroll
    for (int p = 0; p < PF - 1; ++p) {
        xrb[p] = ldcs2(Xr + base + p * V2);
        xib[p] = ldcs2(Xi + base + p * V2);
    }

#pragma unroll 4
    for (int t = 0; t < T; ++t) {
        // Prefetch t+PF-1 into its ring slot (clamped at the tail).
        {
            const int tp   = t + PF - 1;
            const int offp = base + ((tp < T) ? tp : (T - 1)) * V2;
            xrb[tp & (PF - 1)] = ldcs2(Xr + offp);
            xib[tp & (PF - 1)] = ldcs2(Xi + offp);
        }

        const float2 xr = xrb[t & (PF - 1)];
        const float2 xi = xib[t & (PF - 1)];
        const float xrv[2] = {xr.x, xr.y};
        const float xiv[2] = {xi.x, xi.y};

        float orv[2], oiv[2];
#pragma unroll
        for (int j = 0; j < 2; ++j) {
            const float input_r   = HOPF_SCALER * xrv[j] * cs[j];
            const float input_phi = HOPF_SCALER * xiv[j] * sn[j];
            const float rr = r[j];
            r[j]   = rr + ((1.0f - rr * rr) * rr + input_r) * HOPF_DT;
            phi[j] = phi[j] + (omv[j] - input_phi) * HOPF_DT;
            __sincosf(phi[j], &sn[j], &cs[j]);
            orv[j] = r[j] * cs[j];
            oiv[j] = r[j] * sn[j];
        }

        const int off = base + t * V2;
        stcs2(OutR + off, make_float2(orv[0], orv[1]));
        stcs2(OutI + off, make_float2(oiv[0], oiv[1]));
    }
}

extern "C" void kernel_launch(void* const* d_in, const int* in_sizes, int n_in,
                              void* d_out, int out_size)
{
    const float2* Xr = (const float2*)d_in[0];
    const float2* Xi = (const float2*)d_in[1];
    const float2* Om = (const float2*)d_in[2];

    float* out = (float*)d_out;
    const int n_elem = BS * T * CPB;            // 16,777,216 per output tensor
    float2* OutR = (float2*)out;
    float2* OutI = (float2*)(out + n_elem);

    const int n_threads = (BS * CPB) / 2;       // 131072
    hopf_scan_kernel<<<n_threads / 256, 256>>>(Xr, Xi, Om, OutR, OutI);
}